// round 8
// baseline (speedup 1.0000x reference)
#include <cuda_runtime.h>
#include <cstdint>

// FlexMoERouter: logits[8192,16] = x*Wg + image*Wi + text*Wt + audio*Wa + biases
// -> softmax -> top4 (renorm) -> aux loss.
// Output (float32): [0,32768) idx as float, [32768,65536) probs, [65536] aux.

#define B_    4
#define S_    2048
#define H_    1024
#define E_    16
#define TOPK  4
#define NTOK  (B_ * S_)        // 8192
#define TPB   32               // tokens per block
#define NBLK  (NTOK / TPB)     // 256 blocks
#define KC    256              // k per pipeline stage
#define NSTG  16               // 4 modalities x 4 k-chunks
#define NBUF  3
#define XROW  260              // padded smem row stride (floats)

#define XB(b)   ((b) * (TPB * XROW))                 // 3 x 8320 floats
#define SLOFF   (NBUF * TPB * XROW)                  // 24960
#define BSOFF   (SLOFF + TPB * E_)                   // 25472
#define SMEMF   (BSOFF + E_)                         // 25488 floats
#define SMEMB   (SMEMF * 4)                          // 101952 bytes

__device__ float g_Wt[4][E_][H_];       // transposed weights: g_Wt[m][e][k]
__device__ float g_partial[NBLK][E_];   // per-block sum of router_probs per expert
__device__ int   g_count;               // zero-initialized; self-resets each launch

__device__ __forceinline__ void fma2(unsigned long long& acc,
                                     unsigned long long a, unsigned long long b)
{
    asm("fma.rn.f32x2 %0, %1, %2, %0;" : "+l"(acc) : "l"(a), "l"(b));
}
__device__ __forceinline__ void cp16(uint32_t dst_s, const float* src)
{
    asm volatile("cp.async.cg.shared.global [%0], [%1], 16;" :: "r"(dst_s), "l"(src));
}
__device__ __forceinline__ void cp_commit() { asm volatile("cp.async.commit_group;"); }
__device__ __forceinline__ void cp_wait1()  { asm volatile("cp.async.wait_group 1;"); }
__device__ __forceinline__ void cp_wait0()  { asm volatile("cp.async.wait_group 0;"); }

__device__ __forceinline__ float4 f4_add(float4 a, float4 b) {
    return make_float4(a.x + b.x, a.y + b.y, a.z + b.z, a.w + b.w);
}
__device__ __forceinline__ float4 f4_shfl_xor(float4 v, int m) {
    float4 r;
    r.x = __shfl_xor_sync(0xffffffffu, v.x, m);
    r.y = __shfl_xor_sync(0xffffffffu, v.y, m);
    r.z = __shfl_xor_sync(0xffffffffu, v.z, m);
    r.w = __shfl_xor_sync(0xffffffffu, v.w, m);
    return r;
}

// Pre-kernel: transpose W[1024][16] -> g_Wt[m][16][1024].
__global__ void transpose_W(const float* __restrict__ Wg, const float* __restrict__ Wi,
                            const float* __restrict__ Wt, const float* __restrict__ Wa)
{
    const float* Ws[4] = {Wg, Wi, Wt, Wa};
    const int idx = blockIdx.x * 256 + threadIdx.x;   // 0..16383
    const int m = idx >> 12;
    const int r = idx & 4095;
    const int k = r >> 2;
    const int ec = r & 3;
    float4 v = reinterpret_cast<const float4*>(Ws[m])[r];
    g_Wt[m][ec * 4 + 0][k] = v.x;
    g_Wt[m][ec * 4 + 1][k] = v.y;
    g_Wt[m][ec * 4 + 2][k] = v.z;
    g_Wt[m][ec * 4 + 3][k] = v.w;
}

__global__ __launch_bounds__(256, 2)
void router_main(const float* __restrict__ x,   const float* __restrict__ img,
                 const float* __restrict__ txt, const float* __restrict__ aud,
                 const float* __restrict__ bg,  const float* __restrict__ bi,
                 const float* __restrict__ bt,  const float* __restrict__ ba,
                 float* __restrict__ out)
{
    extern __shared__ float sm[];
    __shared__ float4 red_smf[8][4];
    __shared__ float  red_sterm[4];
    __shared__ int    s_isLast;

    const int tid  = threadIdx.x;
    const int lane = tid & 31;
    const int warp = tid >> 5;             // 0..7
    const int tq   = lane & 1;
    const int eq   = (lane >> 1) & 1;
    const int kq   = lane >> 2;            // 0..7
    const int tokB0 = blockIdx.x * TPB;
    const int tokW  = (warp >> 1) * 8 + tq * 4;   // block-local token base
    const int erow0 = (warp & 1) * 8 + eq * 4;    // expert row base

    const float* xs_[4] = {x, img, txt, aud};
    const uint32_t smem_base = (uint32_t)__cvta_generic_to_shared(sm);

    if (tid < E_) sm[BSOFF + tid] = bg[tid] + bi[tid] + bt[tid] + ba[tid];

    unsigned long long acc2[4][4];
#pragma unroll
    for (int t = 0; t < 4; t++)
#pragma unroll
        for (int j = 0; j < 4; j++) acc2[t][j] = 0ull;

    // ---- async x stage issue: 32 rows x 256 k ----
    auto issue = [&](int s) {
        const int m  = s >> 2;
        const int kc = (s & 3) * KC;
        const int b  = s % NBUF;
        const float* xsrc = xs_[m] + (size_t)tokB0 * H_ + kc;
        const uint32_t xd = smem_base + XB(b) * 4;
#pragma unroll
        for (int j = 0; j < 8; j++) {
            const int idx = tid + 256 * j;         // 0..2047
            const int row = idx >> 6;
            const int g   = idx & 63;
            cp16(xd + (uint32_t)(row * XROW + g * 4) * 4, xsrc + row * H_ + g * 4);
        }
        cp_commit();
    };

    issue(0);
    issue(1);
#pragma unroll 1
    for (int s = 0; s < NSTG; s++) {
        if (s == NSTG - 1) cp_wait0(); else cp_wait1();
        __syncthreads();                  // all warps done with buf (s-1) & stage s data visible
        if (s + 2 < NSTG) issue(s + 2);

        const int m  = s >> 2;
        const int kc = (s & 3) * KC;
        const int b  = s % NBUF;
        const ulonglong2* xr[4];
#pragma unroll
        for (int t = 0; t < 4; t++)
            xr[t] = reinterpret_cast<const ulonglong2*>(sm + XB(b) + (tokW + t) * XROW);
        const ulonglong2* wr[4];
#pragma unroll
        for (int j = 0; j < 4; j++)
            wr[j] = reinterpret_cast<const ulonglong2*>(&g_Wt[m][erow0 + j][kc]);

#pragma unroll
        for (int c = 0; c < 8; c++) {
            const int o = c * 8 + kq;              // 16B granule index
            ulonglong2 wv[4];
#pragma unroll
            for (int j = 0; j < 4; j++) wv[j] = __ldg(&wr[j][o]);
            ulonglong2 xv[4];
#pragma unroll
            for (int t = 0; t < 4; t++) xv[t] = xr[t][o];
#pragma unroll
            for (int j = 0; j < 4; j++) {
#pragma unroll
                for (int t = 0; t < 4; t++) {
                    fma2(acc2[t][j], xv[t].x, wv[j].x);
                    fma2(acc2[t][j], xv[t].y, wv[j].y);
                }
            }
        }
    }

    // ---- reduce over kq lanes, write logits ----
    float* sl = sm + SLOFF;                        // [32][16]
#pragma unroll
    for (int t = 0; t < 4; t++) {
        float r[4];
#pragma unroll
        for (int j = 0; j < 4; j++) {
            const unsigned long long v = acc2[t][j];
            float lo = __uint_as_float((unsigned)(v & 0xffffffffull));
            float hi = __uint_as_float((unsigned)(v >> 32));
            float sum = lo + hi;
            sum += __shfl_xor_sync(0xffffffffu, sum, 4);
            sum += __shfl_xor_sync(0xffffffffu, sum, 8);
            sum += __shfl_xor_sync(0xffffffffu, sum, 16);
            r[j] = sum;
        }
        if (kq == 0) {
            float4* dst = reinterpret_cast<float4*>(&sl[(tokW + t) * E_ + erow0]);
            *dst = make_float4(r[0], r[1], r[2], r[3]);
        }
    }
    __syncthreads();

    // ---- epilogue: warp 0, one thread per token ----
    if (tid < TPB) {
        const int g = blockIdx.x * TPB + tid;
        const float* bs = sm + BSOFF;
        float p[E_], q[E_];
        float mx = -1e30f;
#pragma unroll
        for (int e = 0; e < E_; e++) {
            float l = sl[tid * E_ + e] + bs[e];
            p[e] = l;
            mx = fmaxf(mx, l);
        }
        float ssum = 0.0f;
#pragma unroll
        for (int e = 0; e < E_; e++) { p[e] = expf(p[e] - mx); ssum += p[e]; }
        const float inv = 1.0f / ssum;
#pragma unroll
        for (int e = 0; e < E_; e++) { p[e] *= inv; q[e] = p[e]; }

        float tp[TOPK]; int ti[TOPK]; float tsum = 0.0f;
#pragma unroll
        for (int j = 0; j < TOPK; j++) {
            float best = -1.0f; int bidx = 0;
#pragma unroll
            for (int e = 0; e < E_; e++)
                if (p[e] > best) { best = p[e]; bidx = e; }
            tp[j] = best; ti[j] = bidx; tsum += best;
            p[bidx] = -2.0f;
        }
        const float tinv = 1.0f / tsum;
        float4* oi = reinterpret_cast<float4*>(out + (size_t)g * TOPK);
        float4* op = reinterpret_cast<float4*>(out + (size_t)NTOK * TOPK + (size_t)g * TOPK);
        *oi = make_float4((float)ti[0], (float)ti[1], (float)ti[2], (float)ti[3]);
        *op = make_float4(tp[0] * tinv, tp[1] * tinv, tp[2] * tinv, tp[3] * tinv);

#pragma unroll
        for (int e = 0; e < E_; e++) {
            float v = q[e];
            v += __shfl_xor_sync(0xffffffffu, v, 16);
            v += __shfl_xor_sync(0xffffffffu, v, 8);
            v += __shfl_xor_sync(0xffffffffu, v, 4);
            v += __shfl_xor_sync(0xffffffffu, v, 2);
            v += __shfl_xor_sync(0xffffffffu, v, 1);
            if (lane == 0) g_partial[blockIdx.x][e] = v;
        }
    }
    __syncthreads();

    // ---- last block reduces g_partial -> aux loss (fixed order, deterministic) ----
    if (tid == 0) {
        __threadfence();
        int old = atomicAdd(&g_count, 1);
        s_isLast = (old == NBLK - 1);
    }
    __syncthreads();
    if (s_isLast) {
        __threadfence();
        const float4* gp4 = reinterpret_cast<const float4*>(&g_partial[0][0]);
        float4 v = f4_add(f4_add(gp4[tid], gp4[tid + 256]),
                          f4_add(gp4[tid + 512], gp4[tid + 768]));
        v = f4_add(v, f4_shfl_xor(v, 4));
        v = f4_add(v, f4_shfl_xor(v, 8));
        v = f4_add(v, f4_shfl_xor(v, 16));
        if (lane < 4) red_smf[warp][lane] = v;
        __syncthreads();
        if (tid < 4) {
            float4 t = red_smf[0][tid];
#pragma unroll
            for (int w = 1; w < 8; w++) t = f4_add(t, red_smf[w][tid]);
            const float invn = 1.0f / (float)NTOK;
            float s = 0.0f, pe;
            pe = t.x * invn; s += pe * logf(pe * (float)E_ + 1e-9f);
            pe = t.y * invn; s += pe * logf(pe * (float)E_ + 1e-9f);
            pe = t.z * invn; s += pe * logf(pe * (float)E_ + 1e-9f);
            pe = t.w * invn; s += pe * logf(pe * (float)E_ + 1e-9f);
            red_sterm[tid] = s;
        }
        __syncthreads();
        if (tid == 0) {
            out[(size_t)NTOK * TOPK * 2] = red_sterm[0] + red_sterm[1]
                                         + red_sterm[2] + red_sterm[3];
            g_count = 0;                 // reset for next graph replay
        }
    }
}

extern "C" void kernel_launch(void* const* d_in, const int* in_sizes, int n_in,
                              void* d_out, int out_size)
{
    (void)in_sizes; (void)n_in; (void)out_size;
    const float* x   = (const float*)d_in[0];
    const float* img = (const float*)d_in[1];
    const float* txt = (const float*)d_in[2];
    const float* aud = (const float*)d_in[3];
    const float* Wg  = (const float*)d_in[4];
    const float* bg  = (const float*)d_in[5];
    const float* Wi  = (const float*)d_in[6];
    const float* bi  = (const float*)d_in[7];
    const float* Wt  = (const float*)d_in[8];
    const float* bt  = (const float*)d_in[9];
    const float* Wa  = (const float*)d_in[10];
    const float* ba  = (const float*)d_in[11];
    float* out = (float*)d_out;

    cudaFuncSetAttribute(router_main, cudaFuncAttributeMaxDynamicSharedMemorySize, SMEMB);

    transpose_W<<<64, 256>>>(Wg, Wi, Wt, Wa);
    router_main<<<NBLK, 256, SMEMB>>>(x, img, txt, aud, bg, bi, bt, ba, out);
}

// round 9
// speedup vs baseline: 1.2018x; 1.2018x over previous
#include <cuda_runtime.h>
#include <cstdint>

// FlexMoERouter: logits[8192,16] = x*Wg + image*Wi + text*Wt + audio*Wa + biases
// -> softmax -> top4 (renorm) -> aux loss.
// Output (float32): [0,32768) idx as float, [32768,65536) probs, [65536] aux.

#define B_    4
#define S_    2048
#define H_    1024
#define E_    16
#define TOPK  4
#define NTOK  (B_ * S_)        // 8192
#define TPB   64               // tokens per block
#define NBLK  (NTOK / TPB)     // 128 blocks (one wave, 1 CTA/SM)
#define KC    128              // k floats per stage
#define GPS   32               // 16B granules per stage (KC/4)
#define NSTG  32               // 4 modalities x 8 k-chunks
#define NBUF  3
#define XRS   132              // x row stride (floats): 33x16B, odd granule count
#define WRS   132

// dynamic smem (floats)
#define XB(b)   ((b) * (TPB * XRS))                     // 3 x 8448
#define WBo(b)  (NBUF * TPB * XRS + (b) * (E_ * WRS))   // 25344 + b*2112
#define SMEMF   (NBUF * TPB * XRS + NBUF * E_ * WRS)    // 31680 floats
#define SMEMB   (SMEMF * 4)                             // 126720 bytes

__device__ float g_Wt[4][E_][H_];       // transposed weights: g_Wt[m][e][k]
__device__ float g_partial[NBLK][E_];   // per-block sum of router_probs per expert
__device__ int   g_count;               // zero-init; self-resets each launch

__device__ __forceinline__ void fma2(unsigned long long& acc,
                                     unsigned long long a, unsigned long long b)
{
    asm("fma.rn.f32x2 %0, %1, %2, %0;" : "+l"(acc) : "l"(a), "l"(b));
}
__device__ __forceinline__ float fma2_lo(unsigned long long v) {
    return __uint_as_float((unsigned)(v & 0xffffffffull));
}
__device__ __forceinline__ float fma2_hi(unsigned long long v) {
    return __uint_as_float((unsigned)(v >> 32));
}
__device__ __forceinline__ void cp16(uint32_t dst_s, const float* src)
{
    asm volatile("cp.async.cg.shared.global [%0], [%1], 16;" :: "r"(dst_s), "l"(src));
}
__device__ __forceinline__ void cp_commit() { asm volatile("cp.async.commit_group;"); }
__device__ __forceinline__ void cp_wait1()  { asm volatile("cp.async.wait_group 1;"); }
__device__ __forceinline__ void cp_wait0()  { asm volatile("cp.async.wait_group 0;"); }

__device__ __forceinline__ float4 f4_add(float4 a, float4 b) {
    return make_float4(a.x + b.x, a.y + b.y, a.z + b.z, a.w + b.w);
}
__device__ __forceinline__ float4 f4_shfl_xor(float4 v, int m) {
    float4 r;
    r.x = __shfl_xor_sync(0xffffffffu, v.x, m);
    r.y = __shfl_xor_sync(0xffffffffu, v.y, m);
    r.z = __shfl_xor_sync(0xffffffffu, v.z, m);
    r.w = __shfl_xor_sync(0xffffffffu, v.w, m);
    return r;
}

// Pre-kernel: transpose W[1024][16] -> g_Wt[m][16][1024].
__global__ void transpose_W(const float* __restrict__ Wg, const float* __restrict__ Wi,
                            const float* __restrict__ Wt, const float* __restrict__ Wa)
{
    const float* Ws[4] = {Wg, Wi, Wt, Wa};
    const int idx = blockIdx.x * 256 + threadIdx.x;   // 0..16383
    const int m = idx >> 12;
    const int r = idx & 4095;
    const int k = r >> 2;
    const int ec = r & 3;
    float4 v = reinterpret_cast<const float4*>(Ws[m])[r];
    g_Wt[m][ec * 4 + 0][k] = v.x;
    g_Wt[m][ec * 4 + 1][k] = v.y;
    g_Wt[m][ec * 4 + 2][k] = v.z;
    g_Wt[m][ec * 4 + 3][k] = v.w;
}

__global__ __launch_bounds__(256, 1)
void router_main(const float* __restrict__ x,   const float* __restrict__ img,
                 const float* __restrict__ txt, const float* __restrict__ aud,
                 const float* __restrict__ bg,  const float* __restrict__ bi,
                 const float* __restrict__ bt,  const float* __restrict__ ba,
                 float* __restrict__ out)
{
    extern __shared__ float sm[];
    __shared__ float  sl[TPB][E_];       // logits (bias included)
    __shared__ float  bsum[E_];
    __shared__ float  wpart[2][E_];
    __shared__ float4 red_smf[8][4];
    __shared__ float  red_sterm[4];
    __shared__ int    s_isLast;

    const int tid  = threadIdx.x;
    const int lane = tid & 31;
    const int warp = tid >> 5;             // 0..7  (k-granule class: g % 8 == warp)
    const int tokB0 = blockIdx.x * TPB;

    const float* xs_[4] = {x, img, txt, aud};
    const uint32_t smem_base = (uint32_t)__cvta_generic_to_shared(sm);

    if (tid < E_) bsum[tid] = bg[tid] + bi[tid] + bt[tid] + ba[tid];

    // acc2[t][e]: token t = lane + 32*t, expert e; f32x2 over (even-k, odd-k)
    unsigned long long acc2[2][E_];
#pragma unroll
    for (int t = 0; t < 2; t++)
#pragma unroll
        for (int e = 0; e < E_; e++) acc2[t][e] = 0ull;

    // ---- async stage issue: x 64 rows x 128k (32KB) + W 16 rows x 128k (8KB) ----
    auto issue = [&](int s) {
        const int m  = s >> 3;
        const int kc = (s & 7) * KC;
        const int b  = s % NBUF;
        const float* xsrc = xs_[m] + (size_t)tokB0 * H_ + kc;
        const uint32_t xd = smem_base + XB(b) * 4;
#pragma unroll
        for (int j = 0; j < 8; j++) {
            const int idx = tid + 256 * j;         // 0..2047
            const int row = idx >> 5;
            const int g   = idx & 31;
            cp16(xd + (uint32_t)(row * XRS + g * 4) * 4, xsrc + row * H_ + g * 4);
        }
        const float* wsrc = &g_Wt[m][0][kc];
        const uint32_t wd = smem_base + WBo(b) * 4;
#pragma unroll
        for (int j = 0; j < 2; j++) {
            const int idx = tid + 256 * j;         // 0..511
            const int row = idx >> 5;
            const int g   = idx & 31;
            cp16(wd + (uint32_t)(row * WRS + g * 4) * 4, wsrc + row * H_ + g * 4);
        }
        cp_commit();
    };

    issue(0);
    issue(1);
#pragma unroll 1
    for (int s = 0; s < NSTG; s++) {
        if (s == NSTG - 1) cp_wait0(); else cp_wait1();
        __syncthreads();                  // stage s visible; buf (s-1)%3 drained
        if (s + 2 < NSTG) issue(s + 2);

        const int b = s % NBUF;
        const float* xb = sm + XB(b);
        const float* wb = sm + WBo(b);
        const ulonglong2* xr0 = reinterpret_cast<const ulonglong2*>(xb + lane * XRS);
        const ulonglong2* xr1 = reinterpret_cast<const ulonglong2*>(xb + (lane + 32) * XRS);

#pragma unroll
        for (int i = 0; i < 4; i++) {
            const int o = warp + 8 * i;            // this warp's granule in stage
            const ulonglong2 xv0 = xr0[o];
            const ulonglong2 xv1 = xr1[o];
#pragma unroll
            for (int e = 0; e < E_; e++) {
                const ulonglong2 wv =
                    reinterpret_cast<const ulonglong2*>(wb + e * WRS)[o];  // warp-uniform
                fma2(acc2[0][e], xv0.x, wv.x);
                fma2(acc2[0][e], xv0.y, wv.y);
                fma2(acc2[1][e], xv1.x, wv.x);
                fma2(acc2[1][e], xv1.y, wv.y);
            }
        }
    }
    __syncthreads();                       // all compute done; stage bufs reusable

    // ---- cross-warp (k) reduction via smem: red[w][tok][e] over XB region ----
    float* red = sm;                       // 8*64*16 floats = 32KB (fits in stage bufs)
#pragma unroll
    for (int t = 0; t < 2; t++) {
        const int row = lane + 32 * t;
        float4* dst = reinterpret_cast<float4*>(red + warp * (TPB * E_) + row * E_);
#pragma unroll
        for (int q = 0; q < 4; q++) {
            dst[q] = make_float4(
                fma2_lo(acc2[t][q * 4 + 0]) + fma2_hi(acc2[t][q * 4 + 0]),
                fma2_lo(acc2[t][q * 4 + 1]) + fma2_hi(acc2[t][q * 4 + 1]),
                fma2_lo(acc2[t][q * 4 + 2]) + fma2_hi(acc2[t][q * 4 + 2]),
                fma2_lo(acc2[t][q * 4 + 3]) + fma2_hi(acc2[t][q * 4 + 3]));
        }
    }
    __syncthreads();

    {   // 256 threads: each sums 8 warp-partials for (token, expert-quad)
        const int t = tid >> 2;
        const int q = tid & 3;
        float4 s4 = make_float4(0.f, 0.f, 0.f, 0.f);
#pragma unroll
        for (int w = 0; w < 8; w++)
            s4 = f4_add(s4, reinterpret_cast<const float4*>(
                                red + w * (TPB * E_) + t * E_ + q * 4)[0]);
        const float4 bq = reinterpret_cast<const float4*>(bsum)[q];
        reinterpret_cast<float4*>(&sl[t][q * 4])[0] = f4_add(s4, bq);
    }
    __syncthreads();

    // ---- epilogue: threads 0..63, one token each ----
    if (tid < TPB) {
        const int g = blockIdx.x * TPB + tid;
        float p[E_], q[E_];
        float mx = -1e30f;
#pragma unroll
        for (int e = 0; e < E_; e++) {
            float l = sl[tid][e];
            p[e] = l;
            mx = fmaxf(mx, l);
        }
        float ssum = 0.0f;
#pragma unroll
        for (int e = 0; e < E_; e++) { p[e] = expf(p[e] - mx); ssum += p[e]; }
        const float inv = 1.0f / ssum;
#pragma unroll
        for (int e = 0; e < E_; e++) { p[e] *= inv; q[e] = p[e]; }

        float tp[TOPK]; int ti[TOPK]; float tsum = 0.0f;
#pragma unroll
        for (int j = 0; j < TOPK; j++) {
            float best = -1.0f; int bidx = 0;
#pragma unroll
            for (int e = 0; e < E_; e++)
                if (p[e] > best) { best = p[e]; bidx = e; }
            tp[j] = best; ti[j] = bidx; tsum += best;
            p[bidx] = -2.0f;
        }
        const float tinv = 1.0f / tsum;
        float4* oi = reinterpret_cast<float4*>(out + (size_t)g * TOPK);
        float4* op = reinterpret_cast<float4*>(out + (size_t)NTOK * TOPK + (size_t)g * TOPK);
        *oi = make_float4((float)ti[0], (float)ti[1], (float)ti[2], (float)ti[3]);
        *op = make_float4(tp[0] * tinv, tp[1] * tinv, tp[2] * tinv, tp[3] * tinv);

        // per-expert prob sums, warp-local (warp 0: tokens 0-31, warp 1: 32-63)
#pragma unroll
        for (int e = 0; e < E_; e++) {
            float v = q[e];
            v += __shfl_xor_sync(0xffffffffu, v, 16);
            v += __shfl_xor_sync(0xffffffffu, v, 8);
            v += __shfl_xor_sync(0xffffffffu, v, 4);
            v += __shfl_xor_sync(0xffffffffu, v, 2);
            v += __shfl_xor_sync(0xffffffffu, v, 1);
            if (lane == 0) wpart[warp][e] = v;
        }
    }
    __syncthreads();
    if (tid < E_)
        g_partial[blockIdx.x][tid] = wpart[0][tid] + wpart[1][tid];
    __syncthreads();

    // ---- last block reduces g_partial -> aux loss (fixed order, deterministic) ----
    if (tid == 0) {
        __threadfence();
        int old = atomicAdd(&g_count, 1);
        s_isLast = (old == NBLK - 1);
    }
    __syncthreads();
    if (s_isLast) {
        __threadfence();
        // g_partial = 128 x 16 = 512 float4
        const float4* gp4 = reinterpret_cast<const float4*>(&g_partial[0][0]);
        float4 v = f4_add(gp4[tid], gp4[tid + 256]);
        v = f4_add(v, f4_shfl_xor(v, 4));
        v = f4_add(v, f4_shfl_xor(v, 8));
        v = f4_add(v, f4_shfl_xor(v, 16));
        if (lane < 4) red_smf[warp][lane] = v;
        __syncthreads();
        if (tid < 4) {
            float4 t = red_smf[0][tid];
#pragma unroll
            for (int w = 1; w < 8; w++) t = f4_add(t, red_smf[w][tid]);
            const float invn = 1.0f / (float)NTOK;
            float s = 0.0f, pe;
            pe = t.x * invn; s += pe * logf(pe * (float)E_ + 1e-9f);
            pe = t.y * invn; s += pe * logf(pe * (float)E_ + 1e-9f);
            pe = t.z * invn; s += pe * logf(pe * (float)E_ + 1e-9f);
            pe = t.w * invn; s += pe * logf(pe * (float)E_ + 1e-9f);
            red_sterm[tid] = s;
        }
        __syncthreads();
        if (tid == 0) {
            out[(size_t)NTOK * TOPK * 2] = red_sterm[0] + red_sterm[1]
                                         + red_sterm[2] + red_sterm[3];
            g_count = 0;                 // reset for next graph replay
        }
    }
}

extern "C" void kernel_launch(void* const* d_in, const int* in_sizes, int n_in,
                              void* d_out, int out_size)
{
    (void)in_sizes; (void)n_in; (void)out_size;
    const float* x   = (const float*)d_in[0];
    const float* img = (const float*)d_in[1];
    const float* txt = (const float*)d_in[2];
    const float* aud = (const float*)d_in[3];
    const float* Wg  = (const float*)d_in[4];
    const float* bg  = (const float*)d_in[5];
    const float* Wi  = (const float*)d_in[6];
    const float* bi  = (const float*)d_in[7];
    const float* Wt  = (const float*)d_in[8];
    const float* bt  = (const float*)d_in[9];
    const float* Wa  = (const float*)d_in[10];
    const float* ba  = (const float*)d_in[11];
    float* out = (float*)d_out;

    cudaFuncSetAttribute(router_main, cudaFuncAttributeMaxDynamicSharedMemorySize, SMEMB);

    transpose_W<<<64, 256>>>(Wg, Wi, Wt, Wa);
    router_main<<<NBLK, 256, SMEMB>>>(x, img, txt, aud, bg, bi, bt, ba, out);
}